// round 5
// baseline (speedup 1.0000x reference)
#include <cuda_runtime.h>

// Analytic collapse of the reference:
//   channel block is affine: y = a*Hadamard2D(x) + b, with
//     a = dot(out_w, conv_w), b = dot(out_w, conv_b) + out_b
//   _H_MAT is symmetric and _H_MAT @ _H_MAT = I, so the double 2-D transform
//   is identity and the constant transforms to H J H^T = 256 * e0 e0^T:
//     out[e] = a*x[e] + 256*b at patch corners (h%256==0 && w%256==0).
// Corner condition on the float4 index i (e = 4*i): (i & 0x1FE3F) == 0.
//
// R4 lesson: every shape lands ~19.5us with NO counter saturated ->
// exposed memory latency between iterations. This version software-pipelines:
// batch k+1's 4 loads are in flight while batch k is scaled and stored, so
// each warp always has outstanding loads covering its compute.

#ifndef NUM_SMS
#define NUM_SMS 148
#endif
#define CTAS_PER_SM 6
#define BLOCKS (NUM_SMS * CTAS_PER_SM)   // 888
#define THREADS 256
#define STRIDE (BLOCKS * THREADS)        // 227,328
#define N4 (4 * 2048 * 2048 / 4)         // 4,194,304 float4s

__global__ void __launch_bounds__(THREADS, CTAS_PER_SM)
fused_scale_kernel(const float4* __restrict__ in,
                   float4* __restrict__ out,
                   const float* __restrict__ conv_w,
                   const float* __restrict__ conv_b,
                   const float* __restrict__ out_w,
                   const float* __restrict__ out_b) {
    int i = blockIdx.x * THREADS + threadIdx.x;

    // Prologue: first batch of 4 strided loads in flight ASAP.
    float4 cur[4];
#pragma unroll
    for (int j = 0; j < 4; ++j) {
        cur[j] = __ldcg(&in[i + j * STRIDE]);
    }

    // Scalars hidden under the prologue loads (uniform broadcast loads).
    float a = 0.f, b = 0.f;
#pragma unroll
    for (int c = 0; c < 16; ++c) {
        a += __ldg(&conv_w[c]) * __ldg(&out_w[c]);
        b += __ldg(&conv_b[c]) * __ldg(&out_w[c]);
    }
    const float bb = 256.0f * (b + __ldg(&out_b[0]));

    // Pipelined main loop: prefetch batch k+1, then process/store batch k.
    int inext = i + 4 * STRIDE;
    for (; inext + 3 * STRIDE < N4; inext += 4 * STRIDE) {
        float4 nxt[4];
#pragma unroll
        for (int j = 0; j < 4; ++j) {
            nxt[j] = __ldcg(&in[inext + j * STRIDE]);
        }
#pragma unroll
        for (int j = 0; j < 4; ++j) {
            float4 v = cur[j];
            v.x *= a;
            v.y *= a;
            v.z *= a;
            v.w *= a;
            if (((i + j * STRIDE) & 0x1FE3F) == 0) {
                v.x += bb;
            }
            __stcs(&out[i + j * STRIDE], v);
            cur[j] = nxt[j];
        }
        i = inext;
    }
    // Drain the last full batch.
#pragma unroll
    for (int j = 0; j < 4; ++j) {
        float4 v = cur[j];
        v.x *= a;
        v.y *= a;
        v.z *= a;
        v.w *= a;
        if (((i + j * STRIDE) & 0x1FE3F) == 0) {
            v.x += bb;
        }
        __stcs(&out[i + j * STRIDE], v);
    }
    // Remainder (fewer than 4 strides left).
    for (int r = i + 4 * STRIDE; r < N4; r += STRIDE) {
        float4 v = __ldcg(&in[r]);
        v.x *= a;
        v.y *= a;
        v.z *= a;
        v.w *= a;
        if ((r & 0x1FE3F) == 0) {
            v.x += bb;
        }
        __stcs(&out[r], v);
    }
}

extern "C" void kernel_launch(void* const* d_in, const int* in_sizes, int n_in,
                              void* d_out, int out_size) {
    const float* x      = (const float*)d_in[0];
    const float* conv_w = (const float*)d_in[1];
    const float* conv_b = (const float*)d_in[2];
    const float* out_w  = (const float*)d_in[3];
    const float* out_b  = (const float*)d_in[4];
    float* out = (float*)d_out;

    fused_scale_kernel<<<BLOCKS, THREADS>>>((const float4*)x, (float4*)out,
                                            conv_w, conv_b, out_w, out_b);
}

// round 6
// speedup vs baseline: 1.1099x; 1.1099x over previous
#include <cuda_runtime.h>

// Analytic collapse of the reference:
//   channel block is affine: y = a*Hadamard2D(x) + b, with
//     a = dot(out_w, conv_w), b = dot(out_w, conv_b) + out_b
//   _H_MAT is symmetric and _H_MAT @ _H_MAT = I, so the double 2-D transform
//   is identity and the constant transforms to H J H^T = 256 * e0 e0^T:
//     out[e] = a*x[e] + 256*b at patch corners (h%256==0 && w%256==0).
// Corner condition on the float4 index i (e = 4*i): (i & 0x1FE3F) == 0.
//
// R5 model: kernel time is pinned at ~19.4us across all shapes because total
// L2-side traffic (67MB R + 67MB W = 134MB) / 19.4us = 6.9 TB/s = the
// HW-measured full-chip LTS sector-rate ceiling (~6300 B/cyc), which binds
// regardless of DRAM vs L2-hit path. Traffic is irreducible, so this kernel
// just rides the cap as cleanly as possible: exact-divide single-wave grid
// (1024 CTAs x 256 thr x 16 float4 = N4 exactly), no remainder, unroll-4
// batched loads for MLP, no barriers, no prologue serialization.

#define BLOCKS  1024
#define THREADS 256
#define STRIDE  (BLOCKS * THREADS)       // 262,144 float4s
#define ITERS   16                       // 16 * STRIDE = 4,194,304 = N4

__global__ void __launch_bounds__(THREADS)
fused_scale_kernel(const float4* __restrict__ in,
                   float4* __restrict__ out,
                   const float* __restrict__ conv_w,
                   const float* __restrict__ conv_b,
                   const float* __restrict__ out_w,
                   const float* __restrict__ out_b) {
    const int tid = blockIdx.x * THREADS + threadIdx.x;

    // Scalars, computed redundantly per thread (uniform broadcast loads,
    // hidden under the first load batch's latency).
    float a = 0.f, b = 0.f;
#pragma unroll
    for (int c = 0; c < 16; ++c) {
        a += __ldg(&conv_w[c]) * __ldg(&out_w[c]);
        b += __ldg(&conv_b[c]) * __ldg(&out_w[c]);
    }
    const float bb = 256.0f * (b + __ldg(&out_b[0]));

    // 16 float4s per thread in 4 batches of 4 (MLP=4 within each batch).
#pragma unroll
    for (int k = 0; k < ITERS; k += 4) {
        float4 v[4];
#pragma unroll
        for (int j = 0; j < 4; ++j) {
            v[j] = __ldcg(&in[tid + (k + j) * STRIDE]);
        }
#pragma unroll
        for (int j = 0; j < 4; ++j) {
            const int idx = tid + (k + j) * STRIDE;
            v[j].x *= a;
            v[j].y *= a;
            v[j].z *= a;
            v[j].w *= a;
            if ((idx & 0x1FE3F) == 0) {
                v[j].x += bb;
            }
            __stcs(&out[idx], v[j]);
        }
    }
}

extern "C" void kernel_launch(void* const* d_in, const int* in_sizes, int n_in,
                              void* d_out, int out_size) {
    const float* x      = (const float*)d_in[0];
    const float* conv_w = (const float*)d_in[1];
    const float* conv_b = (const float*)d_in[2];
    const float* out_w  = (const float*)d_in[3];
    const float* out_b  = (const float*)d_in[4];
    float* out = (float*)d_out;

    fused_scale_kernel<<<BLOCKS, THREADS>>>((const float4*)x, (float4*)out,
                                            conv_w, conv_b, out_w, out_b);
}

// round 7
// speedup vs baseline: 1.2280x; 1.1064x over previous
#include <cuda_runtime.h>

// Analytic collapse of the reference:
//   channel block is affine: y = a*Hadamard2D(x) + b, with
//     a = dot(out_w, conv_w), b = dot(out_w, conv_b) + out_b
//   _H_MAT is symmetric and _H_MAT @ _H_MAT = I, so the double 2-D transform
//   is identity and the constant transforms to H J H^T = 256 * e0 e0^T:
//     out[e] = a*x[e] + 256*b at patch corners (h%256==0 && w%256==0).
// Corner condition on the float4 index i (e = 4*i): (i & 0x1FE3F) == 0.
//
// Consolidated model (R1-R6): any config with a full resident single wave of
// 8 CTAs/SM rides the full-chip LTS sector-rate ceiling (~6.9 TB/s over the
// irreducible 134MB of L2-side traffic) and lands ~19us; anything that breaks
// the 32-reg/8-CTA budget or adds waves regresses. This is the R4 winner
// (1184 blocks = 148 SMs x 8, launch_bounds(256,8) -> regs 32, occ 85%)
// with the cheaper corner mask and no other cleverness.

#ifndef NUM_SMS
#define NUM_SMS 148
#endif
#define CTAS_PER_SM 8
#define BLOCKS  (NUM_SMS * CTAS_PER_SM)  // 1184
#define THREADS 256
#define STRIDE  (BLOCKS * THREADS)       // 303,104
#define N4      (4 * 2048 * 2048 / 4)    // 4,194,304 float4s

__global__ void __launch_bounds__(THREADS, CTAS_PER_SM)
fused_scale_kernel(const float4* __restrict__ in,
                   float4* __restrict__ out,
                   const float* __restrict__ conv_w,
                   const float* __restrict__ conv_b,
                   const float* __restrict__ out_w,
                   const float* __restrict__ out_b) {
    int i = blockIdx.x * THREADS + threadIdx.x;

    // Scalars, computed redundantly per thread (uniform broadcast loads,
    // hidden under the first batch's load latency by issue order).
    float a = 0.f, b = 0.f;
#pragma unroll
    for (int c = 0; c < 16; ++c) {
        a += __ldg(&conv_w[c]) * __ldg(&out_w[c]);
        b += __ldg(&conv_b[c]) * __ldg(&out_w[c]);
    }
    const float bb = 256.0f * (b + __ldg(&out_b[0]));

    // Main loop: 4 independent float4 streams per iteration (MLP=4).
    // 13.84 iters/thread: 3 full batch-of-4 iterations + up to 2 tail iters.
    for (; i + 3 * STRIDE < N4; i += 4 * STRIDE) {
        float4 v[4];
#pragma unroll
        for (int j = 0; j < 4; ++j) {
            v[j] = __ldcg(&in[i + j * STRIDE]);
        }
#pragma unroll
        for (int j = 0; j < 4; ++j) {
            v[j].x *= a;
            v[j].y *= a;
            v[j].z *= a;
            v[j].w *= a;
            if (((i + j * STRIDE) & 0x1FE3F) == 0) {
                v[j].x += bb;
            }
            __stcs(&out[i + j * STRIDE], v[j]);
        }
    }
    // Tail (up to 2 strided iterations).
    for (; i < N4; i += STRIDE) {
        float4 v = __ldcg(&in[i]);
        v.x *= a;
        v.y *= a;
        v.z *= a;
        v.w *= a;
        if ((i & 0x1FE3F) == 0) {
            v.x += bb;
        }
        __stcs(&out[i], v);
    }
}

extern "C" void kernel_launch(void* const* d_in, const int* in_sizes, int n_in,
                              void* d_out, int out_size) {
    const float* x      = (const float*)d_in[0];
    const float* conv_w = (const float*)d_in[1];
    const float* conv_b = (const float*)d_in[2];
    const float* out_w  = (const float*)d_in[3];
    const float* out_b  = (const float*)d_in[4];
    float* out = (float*)d_out;

    fused_scale_kernel<<<BLOCKS, THREADS>>>((const float4*)x, (float4*)out,
                                            conv_w, conv_b, out_w, out_b);
}